// round 3
// baseline (speedup 1.0000x reference)
#include <cuda_runtime.h>

#define Nn 1024
#define Hh 100
#define Gg 400
#define KE 125
#define Ll 40
#define EPSV 1e-20f

// ---------------- scratch (device globals; no allocation allowed) ----------------
__device__ float g_E[Nn * KE];     // embeddings [1024,125]
__device__ float g_P[Nn * Gg];     // precomputed input-projection gates [1024,400] (reused per layer)
__device__ float g_H0[Nn * Hh];    // layer0 hidden states
__device__ float g_H1[Nn * Hh];    // layer1 hidden states
__device__ float g_u[2 * Hh + 1];  // u1[100], u2[100], c0
__device__ float g_EA[Nn];
__device__ float g_EB[Nn];
__device__ float g_S;

// ---------------- helpers ----------------
__device__ __forceinline__ float tanhap(float x) {
    float r;
    asm("tanh.approx.f32 %0, %1;" : "=f"(r) : "f"(x));
    return r;
}

#define FMA2(acc, a, b) asm("fma.rn.f32x2 %0, %1, %2, %0;" : "+l"(acc) : "l"(a), "l"(b))
// volatile: pins issue order so ptxas cannot batch-hoist all 25 loads (reg blowup -> spills)
#define LDSV2U64(a, b, addr) \
    asm volatile("ld.shared.v2.u64 {%0, %1}, [%2];" : "=l"(a), "=l"(b) : "r"(addr))

__device__ __forceinline__ float unpack_sum(unsigned long long v) {
    float lo, hi;
    asm("mov.b64 {%0, %1}, %2;" : "=f"(lo), "=f"(hi) : "l"(v));
    return lo + hi;
}

// ---------------- K0: embedding gather ----------------
__global__ void gather_emb(const int* __restrict__ wi, const int* __restrict__ ti,
                           const float* __restrict__ wt, const float* __restrict__ tt) {
    int t = blockIdx.x;
    int w = wi[t];
    int g = ti[t];
    for (int j = threadIdx.x; j < KE; j += blockDim.x)
        g_E[t * KE + j] = (j < 100) ? wt[w * 100 + j] : tt[g * 25 + (j - 100)];
}

// ---------------- K1/K3: C[1024,400] = X[1024,K] @ W[400,K]^T + b1 + b2 ----------------
__global__ __launch_bounds__(256) void gemm_bias(const float* __restrict__ X,
                                                 const float* __restrict__ W,
                                                 const float* __restrict__ b1,
                                                 const float* __restrict__ b2,
                                                 float* __restrict__ C, int K) {
    __shared__ float Xs[64 * 127];
    __shared__ float Ws[32 * 127];
    int m0 = blockIdx.y * 64;
    int n0 = blockIdx.x * 32;
    int tid = threadIdx.x;

    for (int idx = tid; idx < 64 * K; idx += 256) {
        int r = idx / K, c = idx - r * K;
        Xs[r * 127 + c] = X[(m0 + r) * K + c];
    }
    for (int idx = tid; idx < 32 * K; idx += 256) {
        int r = idx / K, c = idx - r * K;
        int n = n0 + r;
        Ws[r * 127 + c] = (n < Gg) ? W[n * K + c] : 0.f;
    }
    __syncthreads();

    int ty = tid >> 5, tx = tid & 31;
    float acc[8] = {0, 0, 0, 0, 0, 0, 0, 0};
    for (int k = 0; k < K; k++) {
        float wv = Ws[tx * 127 + k];
#pragma unroll
        for (int r = 0; r < 8; r++)
            acc[r] = fmaf(Xs[(ty + 8 * r) * 127 + k], wv, acc[r]);
    }
    int n = n0 + tx;
    if (n < Gg) {
        float bb = b1[n] + b2[n];
#pragma unroll
        for (int r = 0; r < 8; r++)
            C[(m0 + ty + 8 * r) * Gg + n] = acc[r] + bb;
    }
}

// ---------------- K2/K4: sequential LSTM recurrence (single CTA, 416 thr) ----------------
// P holds x_t @ W_ih^T + b_ih + b_hh. Gate nonlinearities folded into the 400 dot
// threads (1 MUFU each); the tid<100 update phase has a single tanh on its chain.
__global__ __launch_bounds__(416, 1) void lstm_rec(const float* __restrict__ Whh,
                                                   const float* __restrict__ P,
                                                   float* __restrict__ Hout) {
    __shared__ __align__(16) float h_sh[Hh];
    __shared__ float act_sh[Gg];
    int tid = threadIdx.x;
    int gtype = tid / 100;  // 0:i 1:f 2:g 3:o

    // 100 weights per thread, packed as 50 x f32x2 (100 regs)
    unsigned long long w2[50];
    if (tid < Gg) {
        const ulonglong2* Wr = reinterpret_cast<const ulonglong2*>(Whh + tid * Hh);
#pragma unroll
        for (int j = 0; j < 25; j++) {
            ulonglong2 v = Wr[j];
            w2[2 * j] = v.x;
            w2[2 * j + 1] = v.y;
        }
    }
    float c = 0.f;
    if (tid < Hh) h_sh[tid] = 0.f;
    unsigned h_base = (unsigned)__cvta_generic_to_shared(h_sh);
    __syncthreads();

    float p = (tid < Gg) ? P[tid] : 0.f;  // P row for t=0
    for (int t = 0; t < Nn; t++) {
        float pn = 0.f;
        if (tid < Gg && t + 1 < Nn) pn = P[(t + 1) * Gg + tid];  // prefetch next row

        if (tid < Gg) {
            unsigned long long ha[25], hb[25];
            unsigned long long a0 = 0ull, a1 = 0ull, a2 = 0ull, a3 = 0ull;
            // depth-3 pinned pipeline: at most ~6 u64 temps live
            LDSV2U64(ha[0], hb[0], h_base);
            LDSV2U64(ha[1], hb[1], h_base + 16);
            LDSV2U64(ha[2], hb[2], h_base + 32);
#pragma unroll
            for (int j = 0; j < 25; j++) {
                if (j + 3 < 25) LDSV2U64(ha[j + 3], hb[j + 3], h_base + 16 * (j + 3));
                if (j & 1) {
                    FMA2(a2, w2[2 * j], ha[j]);
                    FMA2(a3, w2[2 * j + 1], hb[j]);
                } else {
                    FMA2(a0, w2[2 * j], ha[j]);
                    FMA2(a1, w2[2 * j + 1], hb[j]);
                }
            }
            float g = (unpack_sum(a0) + unpack_sum(a1)) + (unpack_sum(a2) + unpack_sum(a3)) + p;
            // gate nonlinearity here (400-way parallel): sigmoid(x)=0.5+0.5*tanh(0.5x)
            float r = (gtype == 2) ? tanhap(g) : fmaf(0.5f, tanhap(0.5f * g), 0.5f);
            act_sh[tid] = r;
        }
        __syncthreads();
        if (tid < Hh) {
            float si = act_sh[tid];
            float sf = act_sh[tid + 100];
            float tg = act_sh[tid + 200];
            float so = act_sh[tid + 300];
            c = fmaf(sf, c, si * tg);
            float hk = so * tanhap(c);
            h_sh[tid] = hk;
            Hout[t * Hh + tid] = hk;
        }
        __syncthreads();
        p = pn;
    }
}

// ---------------- K5a: fold scorer weights ----------------
__global__ void prep_u(const float* __restrict__ Wh2h, const float* __restrict__ bh2h,
                       const float* __restrict__ Wsc, const float* __restrict__ bsc) {
    int k = threadIdx.x;
    if (k < Hh) {
        float u1 = 0.f, u2 = 0.f;
        for (int m = 0; m < Hh; m++) {
            float s = Wsc[m];
            u1 = fmaf(Wh2h[m * 200 + k], s, u1);
            u2 = fmaf(Wh2h[m * 200 + 100 + k], s, u2);
        }
        g_u[k] = u1;
        g_u[100 + k] = u2;
    }
    if (k == 0) {
        float c0 = bsc[0];
        for (int m = 0; m < Hh; m++) c0 = fmaf(bh2h[m], Wsc[m], c0);
        g_u[200] = c0;
    }
}

// ---------------- K5b: EA/EB/S ----------------
__global__ __launch_bounds__(1024) void score_vec() {
    __shared__ float red[Nn];
    int i = threadIdx.x;
    const float* h = g_H1 + i * Hh;
    float sA = 0.f, sB = 0.f;
    for (int j = 0; j < Hh; j++) {
        float hv = h[j];
        sA = fmaf(hv, g_u[j], sA);
        sB = fmaf(hv, g_u[100 + j], sB);
    }
    float ea = __expf(sA);
    float eb = __expf(sB + g_u[200]);
    g_EA[i] = ea;
    g_EB[i] = eb;
    red[i] = ea;
    __syncthreads();
    for (int s = 512; s > 0; s >>= 1) {
        if (i < s) red[i] += red[i + s];
        __syncthreads();
    }
    if (i == 0) g_S = red[0];
}

// ---------------- K5c: scores ----------------
__global__ void fill_scores(float* __restrict__ out) {
    int i = blockIdx.x;
    float ea = g_EA[i];
    float S = g_S;
    for (int j = threadIdx.x; j < Nn; j += blockDim.x) {
        float eb = g_EB[j];
        out[i * Nn + j] = __fdividef(ea * eb, fmaf(S, eb, EPSV));
    }
}

// ---------------- K5d: labels ----------------
__global__ void fill_labels(const float* __restrict__ Wlab, const float* __restrict__ blab,
                            float* __restrict__ out) {
    __shared__ float hsh[Hh];
    __shared__ float esh[Ll];
    int r = blockIdx.x;  // 0..1022
    int tid = threadIdx.x;
    const float* h = g_H1 + (r + 1) * Hh;
    for (int j = tid; j < Hh; j += 64) hsh[j] = h[j];
    __syncthreads();
    if (tid < Ll) {
        float a = blab[tid];
        const float* wr = Wlab + tid * Hh;
        for (int j = 0; j < Hh; j++) a = fmaf(hsh[j], wr[j], a);
        esh[tid] = __expf(a);
    }
    __syncthreads();
    if (tid < Ll) {
        float s = 0.f;
        for (int j = 0; j < Ll; j++) s += esh[j];
        out[Nn * Nn + r * Ll + tid] = __fdividef(esh[tid], s + EPSV);
    }
}

// ---------------- launch ----------------
extern "C" void kernel_launch(void* const* d_in, const int* in_sizes, int n_in,
                              void* d_out, int out_size) {
    const int* wi = (const int*)d_in[0];
    const int* ti = (const int*)d_in[1];
    const float* wt = (const float*)d_in[2];
    const float* tt = (const float*)d_in[3];
    const float* Wih0 = (const float*)d_in[4];
    const float* Whh0 = (const float*)d_in[5];
    const float* bih0 = (const float*)d_in[6];
    const float* bhh0 = (const float*)d_in[7];
    const float* Wih1 = (const float*)d_in[8];
    const float* Whh1 = (const float*)d_in[9];
    const float* bih1 = (const float*)d_in[10];
    const float* bhh1 = (const float*)d_in[11];
    const float* Wh2h = (const float*)d_in[12];
    const float* bh2h = (const float*)d_in[13];
    const float* Wsc = (const float*)d_in[14];
    const float* bsc = (const float*)d_in[15];
    const float* Wlab = (const float*)d_in[16];
    const float* blab = (const float*)d_in[17];
    float* out = (float*)d_out;

    float *pE, *pP, *pH0, *pH1;
    cudaGetSymbolAddress((void**)&pE, g_E);
    cudaGetSymbolAddress((void**)&pP, g_P);
    cudaGetSymbolAddress((void**)&pH0, g_H0);
    cudaGetSymbolAddress((void**)&pH1, g_H1);

    dim3 gg(13, 16);

    gather_emb<<<Nn, 128>>>(wi, ti, wt, tt);
    gemm_bias<<<gg, 256>>>(pE, Wih0, bih0, bhh0, pP, KE);
    lstm_rec<<<1, 416>>>(Whh0, pP, pH0);
    gemm_bias<<<gg, 256>>>(pH0, Wih1, bih1, bhh1, pP, Hh);
    lstm_rec<<<1, 416>>>(Whh1, pP, pH1);
    prep_u<<<1, 128>>>(Wh2h, bh2h, Wsc, bsc);
    score_vec<<<1, 1024>>>();
    fill_scores<<<Nn, 256>>>(out);
    fill_labels<<<Nn - 1, 64>>>(Wlab, blab, out);
}

// round 4
// speedup vs baseline: 1.2077x; 1.2077x over previous
#include <cuda_runtime.h>

#define Nn 1024
#define Hh 100
#define Gg 400
#define KE 125
#define Ll 40
#define EPSV 1e-20f

// ---------------- scratch (device globals; no allocation allowed) ----------------
__device__ float g_E[Nn * KE];     // embeddings [1024,125]
__device__ float g_P[Nn * Gg];     // layer0 input projection (gemm output)
__device__ float g_P1[Nn * Gg];    // layer1 input projection (produced by pipe CTA B)
__device__ float g_H0[Nn * Hh];    // layer0 hidden states
__device__ float g_H1[Nn * Hh];    // layer1 hidden states
__device__ int g_flag0[Nn];        // h0[t] ready
__device__ int g_flag1[Nn];        // P1[t] ready
__device__ float g_u[2 * Hh + 1];
__device__ float g_EA[Nn];
__device__ float g_EB[Nn];
__device__ float g_S;

// ---------------- helpers ----------------
__device__ __forceinline__ float tanhap(float x) {
    float r;
    asm("tanh.approx.f32 %0, %1;" : "=f"(r) : "f"(x));
    return r;
}
#define FMA2(acc, a, b) asm("fma.rn.f32x2 %0, %1, %2, %0;" : "+l"(acc) : "l"(a), "l"(b))
__device__ __forceinline__ float unpack_sum(unsigned long long v) {
    float lo, hi;
    asm("mov.b64 {%0, %1}, %2;" : "=f"(lo), "=f"(hi) : "l"(v));
    return lo + hi;
}
__device__ __forceinline__ void spin_flag(const int* f) {
    int v;
    do { asm volatile("ld.acquire.gpu.b32 %0, [%1];" : "=r"(v) : "l"(f) : "memory"); } while (v == 0);
}
__device__ __forceinline__ void set_flag(int* f) {
    asm volatile("st.release.gpu.b32 [%0], %1;" :: "l"(f), "r"(1) : "memory");
}
__device__ __forceinline__ float4 ldg_cg4(const float4* p) {
    float4 v;
    asm volatile("ld.global.cg.v4.f32 {%0,%1,%2,%3}, [%4];"
                 : "=f"(v.x), "=f"(v.y), "=f"(v.z), "=f"(v.w) : "l"(p));
    return v;
}

// ---------------- K0: embedding gather ----------------
__global__ void gather_emb(const int* __restrict__ wi, const int* __restrict__ ti,
                           const float* __restrict__ wt, const float* __restrict__ tt) {
    int t = blockIdx.x;
    int w = wi[t];
    int g = ti[t];
    for (int j = threadIdx.x; j < KE; j += blockDim.x)
        g_E[t * KE + j] = (j < 100) ? wt[w * 100 + j] : tt[g * 25 + (j - 100)];
}

// ---------------- K0b: zero pipeline flags (must run each launch, before pipe) ----------------
__global__ void zero_flags() {
    int i = threadIdx.x;
    g_flag0[i] = 0;
    g_flag1[i] = 0;
}

// ---------------- K1: P0[1024,400] = E[1024,125] @ Wih0^T + b_ih0 + b_hh0 ----------------
__global__ __launch_bounds__(256) void gemm_bias(const float* __restrict__ X,
                                                 const float* __restrict__ W,
                                                 const float* __restrict__ b1,
                                                 const float* __restrict__ b2,
                                                 float* __restrict__ C, int K) {
    __shared__ float Xs[64 * 127];
    __shared__ float Ws[32 * 127];
    int m0 = blockIdx.y * 64;
    int n0 = blockIdx.x * 32;
    int tid = threadIdx.x;

    for (int idx = tid; idx < 64 * K; idx += 256) {
        int r = idx / K, c = idx - r * K;
        Xs[r * 127 + c] = X[(m0 + r) * K + c];
    }
    for (int idx = tid; idx < 32 * K; idx += 256) {
        int r = idx / K, c = idx - r * K;
        int n = n0 + r;
        Ws[r * 127 + c] = (n < Gg) ? W[n * K + c] : 0.f;
    }
    __syncthreads();

    int ty = tid >> 5, tx = tid & 31;
    float acc[8] = {0, 0, 0, 0, 0, 0, 0, 0};
    for (int k = 0; k < K; k++) {
        float wv = Ws[tx * 127 + k];
#pragma unroll
        for (int r = 0; r < 8; r++)
            acc[r] = fmaf(Xs[(ty + 8 * r) * 127 + k], wv, acc[r]);
    }
    int n = n0 + tx;
    if (n < Gg) {
        float bb = b1[n] + b2[n];
#pragma unroll
        for (int r = 0; r < 8; r++)
            C[(m0 + ty + 8 * r) * Gg + n] = acc[r] + bb;
    }
}

// ---------------- K2: 3-stage cross-SM LSTM pipeline ----------------
// grid = 3 CTAs x 832 threads (800 compute = 2 threads/row, 1 prefetch warp).
//   CTA 0 (A): layer0 recurrence. in: pbuf <- g_P rows (no flag). out: h0 -> g_H0 + flag0.
//   CTA 1 (B): layer1 input projection. in: hbuf <- g_H0 rows (flag0). out: g_P1 + flag1.
//   CTA 2 (C): layer1 recurrence. in: pbuf <- g_P1 rows (flag1). out: g_H1.
// Reg budget: 65536/832 = 78/thread; compute thread holds <=26 u64 weights + 2 u64 accs.
__global__ __launch_bounds__(832, 1) void lstm_pipe(const float* __restrict__ Whh0,
                                                    const float* __restrict__ Wih1,
                                                    const float* __restrict__ Whh1,
                                                    const float* __restrict__ bih1,
                                                    const float* __restrict__ bhh1) {
    __shared__ __align__(16) float h_sh[Hh];        // A/C: own hidden state
    __shared__ __align__(16) float hbuf[2][Hh];     // B: double-buffered h0 row
    __shared__ __align__(16) float pbuf[2][Gg];     // A/C: double-buffered additive row
    __shared__ __align__(16) float bias_sh[Gg];     // B: b_ih1 + b_hh1
    __shared__ __align__(16) float part_sh[800];    // per-half-row partials
    __shared__ __align__(16) float act_sh[Gg];      // A/C: activated gates

    const int role = blockIdx.x;  // 0=A, 1=B, 2=C
    const int tid = threadIdx.x;
    const bool iscomp = tid < 800;
    const int row = (tid < 400) ? tid : tid - 400;   // valid when iscomp
    const int q = (tid < 400) ? 0 : 1;               // half: q0 = elems 0..51, q1 = 52..99
    const int nf4 = q ? 12 : 13;
    const int off = q ? 52 : 0;

    const float* W = (role == 0) ? Whh0 : (role == 1) ? Wih1 : Whh1;
    const float* Pin = (role == 0) ? g_P : g_P1;     // A/C additive-row source
    float* Hout = (role == 0) ? g_H0 : g_H1;         // A/C h destination

    // load weights into registers (<= 26 u64)
    unsigned long long wv[26];
    if (iscomp) {
        const ulonglong2* Wr = reinterpret_cast<const ulonglong2*>(W + row * Hh + off);
#pragma unroll
        for (int j = 0; j < 13; j++)
            if (j < nf4) { ulonglong2 v = Wr[j]; wv[2 * j] = v.x; wv[2 * j + 1] = v.y; }
    }

    float c = 0.f;
    if (role != 1 && tid < Hh) h_sh[tid] = 0.f;
    if (role == 1 && tid < Gg) bias_sh[tid] = bih1[tid] + bhh1[tid];

    // prologue prefetch of row 0
    if (!iscomp) {
        int lane = tid - 800;
        if (role == 0) {
            const float4* s = reinterpret_cast<const float4*>(g_P);
            float4* d = reinterpret_cast<float4*>(pbuf[0]);
            d[lane] = s[lane]; d[lane + 32] = s[lane + 32]; d[lane + 64] = s[lane + 64];
            if (lane < 4) d[lane + 96] = s[lane + 96];
        } else if (role == 1) {
            spin_flag(g_flag0);
            const float4* s = reinterpret_cast<const float4*>(g_H0);
            float4* d = reinterpret_cast<float4*>(hbuf[0]);
            if (lane < 25) d[lane] = ldg_cg4(s + lane);
        } else {
            spin_flag(g_flag1);
            const float4* s = reinterpret_cast<const float4*>(g_P1);
            float4* d = reinterpret_cast<float4*>(pbuf[0]);
            d[lane] = ldg_cg4(s + lane);
            d[lane + 32] = ldg_cg4(s + lane + 32);
            d[lane + 64] = ldg_cg4(s + lane + 64);
            if (lane < 4) d[lane + 96] = ldg_cg4(s + lane + 96);
        }
    }
    __syncthreads();

    for (int t = 0; t < Nn; t++) {
        const int buf = t & 1, nbuf = buf ^ 1;

        // -------- phase 1: half-row dots (compute) / prefetch row t+1 (warp 25) --------
        if (iscomp) {
            const float* din = (role == 1) ? hbuf[buf] : h_sh;
            const ulonglong2* h2 = reinterpret_cast<const ulonglong2*>(din + off);
            unsigned long long a0 = 0ull, a1 = 0ull;
#pragma unroll
            for (int j = 0; j < 13; j++)
                if (j < nf4) {
                    ulonglong2 hv = h2[j];  // LDS.128 broadcast
                    FMA2(a0, wv[2 * j], hv.x);
                    FMA2(a1, wv[2 * j + 1], hv.y);
                }
            part_sh[row * 2 + q] = unpack_sum(a0) + unpack_sum(a1);
        } else if (t + 1 < Nn) {
            int lane = tid - 800;
            if (role == 0) {
                const float4* s = reinterpret_cast<const float4*>(g_P + (t + 1) * Gg);
                float4* d = reinterpret_cast<float4*>(pbuf[nbuf]);
                d[lane] = s[lane]; d[lane + 32] = s[lane + 32]; d[lane + 64] = s[lane + 64];
                if (lane < 4) d[lane + 96] = s[lane + 96];
            } else if (role == 1) {
                spin_flag(g_flag0 + t + 1);
                const float4* s = reinterpret_cast<const float4*>(g_H0 + (t + 1) * Hh);
                float4* d = reinterpret_cast<float4*>(hbuf[nbuf]);
                if (lane < 25) d[lane] = ldg_cg4(s + lane);
            } else {
                spin_flag(g_flag1 + t + 1);
                const float4* s = reinterpret_cast<const float4*>(g_P1 + (t + 1) * Gg);
                float4* d = reinterpret_cast<float4*>(pbuf[nbuf]);
                d[lane] = ldg_cg4(s + lane);
                d[lane + 32] = ldg_cg4(s + lane + 32);
                d[lane + 64] = ldg_cg4(s + lane + 64);
                if (lane < 4) d[lane + 96] = ldg_cg4(s + lane + 96);
            }
        }
        __syncthreads();

        // -------- phase 2: combine halves (+ row add / bias), nonlinearity or store --------
        if (tid < Gg) {
            float2 pp = reinterpret_cast<const float2*>(part_sh)[tid];
            if (role == 1) {
                g_P1[t * Gg + tid] = pp.x + pp.y + bias_sh[tid];
            } else {
                float gv = pp.x + pp.y + pbuf[buf][tid];
                int gt = tid / 100;  // 0:i 1:f 2:g 3:o
                act_sh[tid] = (gt == 2) ? tanhap(gv) : fmaf(0.5f, tanhap(0.5f * gv), 0.5f);
            }
        }
        __syncthreads();

        if (role == 1) {
            if (tid == 0) set_flag(g_flag1 + t);
        } else {
            // -------- phase 3: cell/hidden update (A/C) --------
            if (tid < Hh) {
                float si = act_sh[tid];
                float sf = act_sh[tid + 100];
                float tg = act_sh[tid + 200];
                float so = act_sh[tid + 300];
                c = fmaf(sf, c, si * tg);
                float hk = so * tanhap(c);
                h_sh[tid] = hk;
                Hout[t * Hh + tid] = hk;
            }
            __syncthreads();
            if (role == 0 && tid == 0) set_flag(g_flag0 + t);
        }
    }
}

// ---------------- K5a: fold scorer weights ----------------
__global__ void prep_u(const float* __restrict__ Wh2h, const float* __restrict__ bh2h,
                       const float* __restrict__ Wsc, const float* __restrict__ bsc) {
    int k = threadIdx.x;
    if (k < Hh) {
        float u1 = 0.f, u2 = 0.f;
        for (int m = 0; m < Hh; m++) {
            float s = Wsc[m];
            u1 = fmaf(Wh2h[m * 200 + k], s, u1);
            u2 = fmaf(Wh2h[m * 200 + 100 + k], s, u2);
        }
        g_u[k] = u1;
        g_u[100 + k] = u2;
    }
    if (k == 0) {
        float c0 = bsc[0];
        for (int m = 0; m < Hh; m++) c0 = fmaf(bh2h[m], Wsc[m], c0);
        g_u[200] = c0;
    }
}

// ---------------- K5b: EA/EB/S ----------------
__global__ __launch_bounds__(1024) void score_vec() {
    __shared__ float red[Nn];
    int i = threadIdx.x;
    const float* h = g_H1 + i * Hh;
    float sA = 0.f, sB = 0.f;
    for (int j = 0; j < Hh; j++) {
        float hv = h[j];
        sA = fmaf(hv, g_u[j], sA);
        sB = fmaf(hv, g_u[100 + j], sB);
    }
    float ea = __expf(sA);
    float eb = __expf(sB + g_u[200]);
    g_EA[i] = ea;
    g_EB[i] = eb;
    red[i] = ea;
    __syncthreads();
    for (int s = 512; s > 0; s >>= 1) {
        if (i < s) red[i] += red[i + s];
        __syncthreads();
    }
    if (i == 0) g_S = red[0];
}

// ---------------- K5c: scores ----------------
__global__ void fill_scores(float* __restrict__ out) {
    int i = blockIdx.x;
    float ea = g_EA[i];
    float S = g_S;
    for (int j = threadIdx.x; j < Nn; j += blockDim.x) {
        float eb = g_EB[j];
        out[i * Nn + j] = __fdividef(ea * eb, fmaf(S, eb, EPSV));
    }
}

// ---------------- K5d: labels ----------------
__global__ void fill_labels(const float* __restrict__ Wlab, const float* __restrict__ blab,
                            float* __restrict__ out) {
    __shared__ float hsh[Hh];
    __shared__ float esh[Ll];
    int r = blockIdx.x;  // 0..1022
    int tid = threadIdx.x;
    const float* h = g_H1 + (r + 1) * Hh;
    for (int j = tid; j < Hh; j += 64) hsh[j] = h[j];
    __syncthreads();
    if (tid < Ll) {
        float a = blab[tid];
        const float* wr = Wlab + tid * Hh;
        for (int j = 0; j < Hh; j++) a = fmaf(hsh[j], wr[j], a);
        esh[tid] = __expf(a);
    }
    __syncthreads();
    if (tid < Ll) {
        float s = 0.f;
        for (int j = 0; j < Ll; j++) s += esh[j];
        out[Nn * Nn + r * Ll + tid] = __fdividef(esh[tid], s + EPSV);
    }
}

// ---------------- launch ----------------
extern "C" void kernel_launch(void* const* d_in, const int* in_sizes, int n_in,
                              void* d_out, int out_size) {
    const int* wi = (const int*)d_in[0];
    const int* ti = (const int*)d_in[1];
    const float* wt = (const float*)d_in[2];
    const float* tt = (const float*)d_in[3];
    const float* Wih0 = (const float*)d_in[4];
    const float* Whh0 = (const float*)d_in[5];
    const float* bih0 = (const float*)d_in[6];
    const float* bhh0 = (const float*)d_in[7];
    const float* Wih1 = (const float*)d_in[8];
    const float* Whh1 = (const float*)d_in[9];
    const float* bih1 = (const float*)d_in[10];
    const float* bhh1 = (const float*)d_in[11];
    const float* Wh2h = (const float*)d_in[12];
    const float* bh2h = (const float*)d_in[13];
    const float* Wsc = (const float*)d_in[14];
    const float* bsc = (const float*)d_in[15];
    const float* Wlab = (const float*)d_in[16];
    const float* blab = (const float*)d_in[17];
    float* out = (float*)d_out;

    float *pE, *pP;
    cudaGetSymbolAddress((void**)&pE, g_E);
    cudaGetSymbolAddress((void**)&pP, g_P);

    dim3 gg(13, 16);

    gather_emb<<<Nn, 128>>>(wi, ti, wt, tt);
    zero_flags<<<1, Nn>>>();
    gemm_bias<<<gg, 256>>>(pE, Wih0, bih0, bhh0, pP, KE);
    lstm_pipe<<<3, 832>>>(Whh0, Wih1, Whh1, bih1, bhh1);
    prep_u<<<1, 128>>>(Wh2h, bh2h, Wsc, bsc);
    score_vec<<<1, 1024>>>();
    fill_scores<<<Nn, 256>>>(out);
    fill_labels<<<Nn - 1, 64>>>(Wlab, blab, out);
}